// round 2
// baseline (speedup 1.0000x reference)
#include <cuda_runtime.h>
#include <cstdint>

// Haar DWT2D, fused single pass, wide version.
// Input:  x  (16, 1, 2048, 2048) fp32
// Output: [ll | lh | hl | hh], each (16,1,1024,1024) fp32, concatenated.
//
// Each thread handles 4 adjacent output columns (8 input columns):
//   4x LDG.128 in (two per input row), 4x STG.128 out (one per subband).
// All loads/stores use streaming cache hints (no reuse, 512MB > L2).

#define B_  16
#define H_  2048
#define W_  2048
#define HO  (H_/2)        // 1024
#define WO  (W_/2)        // 1024
#define QUADS_PER_ROW (WO/4)  // 256 threads per output row

__device__ __forceinline__ float safef(float v) {
    return isfinite(v) ? v : 0.0f;
}

__global__ __launch_bounds__(256)
void dwt2d_haar_kernel(const float* __restrict__ x, float* __restrict__ out) {
    // tid -> (b, i, j4): j4 indexes a group of 4 output columns.
    // All dims are powers of two; compiler lowers %// to shifts.
    const uint32_t tid = blockIdx.x * 256u + threadIdx.x;   // max 2^22, fits u32
    const uint32_t j4 = tid & (QUADS_PER_ROW - 1);
    const uint32_t i  = (tid >> 8) & (HO - 1);
    const uint32_t b  = tid >> 18;

    // input: rows 2i, 2i+1; cols 8*j4 .. 8*j4+7
    const int64_t in_base = (int64_t)b * (H_ * W_) + (int64_t)(2 * i) * W_ + 8 * j4;
    const float4* p0 = reinterpret_cast<const float4*>(x + in_base);
    const float4* p1 = reinterpret_cast<const float4*>(x + in_base + W_);

    // front-batch all 4 loads for MLP
    float4 t0 = __ldcs(p0);      // top row, blocks 0,1
    float4 t1 = __ldcs(p0 + 1);  // top row, blocks 2,3
    float4 u0 = __ldcs(p1);      // bottom row, blocks 0,1
    float4 u1 = __ldcs(p1 + 1);  // bottom row, blocks 2,3

    float a[4], bb[4], c[4], d[4];
    a[0] = safef(t0.x); bb[0] = safef(t0.y); c[0] = safef(u0.x); d[0] = safef(u0.y);
    a[1] = safef(t0.z); bb[1] = safef(t0.w); c[1] = safef(u0.z); d[1] = safef(u0.w);
    a[2] = safef(t1.x); bb[2] = safef(t1.y); c[2] = safef(u1.x); d[2] = safef(u1.y);
    a[3] = safef(t1.z); bb[3] = safef(t1.w); c[3] = safef(u1.z); d[3] = safef(u1.w);

    float4 ll, lh, hl, hh;
    float* llp = &ll.x; float* lhp = &lh.x; float* hlp = &hl.x; float* hhp = &hh.x;
    #pragma unroll
    for (int k = 0; k < 4; k++) {
        const float h = 0.5f;
        llp[k] = h * ( a[k] + bb[k] + c[k] + d[k]);
        lhp[k] = h * (-a[k] + bb[k] - c[k] + d[k]);
        hlp[k] = h * (-a[k] - bb[k] + c[k] + d[k]);
        hhp[k] = h * ( a[k] - bb[k] - c[k] + d[k]);
    }

    const int64_t plane = (int64_t)B_ * HO * WO;   // 16M elems per subband
    const int64_t o = (int64_t)b * (HO * WO) + (int64_t)i * WO + 4 * j4;

    __stcs(reinterpret_cast<float4*>(out + o),             ll);
    __stcs(reinterpret_cast<float4*>(out + plane + o),     lh);
    __stcs(reinterpret_cast<float4*>(out + 2 * plane + o), hl);
    __stcs(reinterpret_cast<float4*>(out + 3 * plane + o), hh);
}

extern "C" void kernel_launch(void* const* d_in, const int* in_sizes, int n_in,
                              void* d_out, int out_size) {
    const float* x = (const float*)d_in[0];
    float* out = (float*)d_out;

    const int64_t total = (int64_t)B_ * HO * QUADS_PER_ROW;  // 4,194,304 threads
    const int threads = 256;
    const int blocks = (int)(total / threads);               // 16384, exact
    dwt2d_haar_kernel<<<blocks, threads>>>(x, out);
}

// round 3
// speedup vs baseline: 1.0008x; 1.0008x over previous
#include <cuda_runtime.h>
#include <cstdint>

// Haar DWT2D, fused single pass, 2x4-tile version (MLP=8).
// Input:  x  (16, 1, 2048, 2048) fp32
// Output: [ll | lh | hl | hh], each (16,1,1024,1024) fp32, concatenated.
//
// Each thread handles a 2x4 tile of output pixels (4 input rows x 8 cols):
//   8x LDG.128 front-batched (MLP=8), 8x STG.128 (two rows x four subbands).

#define B_  16
#define H_  2048
#define W_  2048
#define HO  (H_/2)            // 1024
#define WO  (W_/2)            // 1024
#define QUADS_PER_ROW (WO/4)  // 256
#define ROWPAIRS (HO/2)       // 512 row-pairs per image

__device__ __forceinline__ float safef(float v) {
    return isfinite(v) ? v : 0.0f;
}

__device__ __forceinline__ float4 haar_row(float4 top, float4 bot, int which) {
    // top = (a0,b0,a1,b1), bot = (c0,d0,c1,d1) for two 2x2 blocks
    float a0 = safef(top.x), b0 = safef(top.y), a1 = safef(top.z), b1 = safef(top.w);
    float c0 = safef(bot.x), d0 = safef(bot.y), c1 = safef(bot.z), d1 = safef(bot.w);
    const float h = 0.5f;
    float4 r;
    switch (which) {
        case 0: r.x = h*( a0+b0+c0+d0); r.y = h*( a1+b1+c1+d1); break; // ll
        case 1: r.x = h*(-a0+b0-c0+d0); r.y = h*(-a1+b1-c1+d1); break; // lh
        case 2: r.x = h*(-a0-b0+c0+d0); r.y = h*(-a1-b1+c1+d1); break; // hl
        default:r.x = h*( a0-b0-c0+d0); r.y = h*( a1-b1-c1+d1); break; // hh
    }
    return r;
}

__global__ __launch_bounds__(256)
void dwt2d_haar_kernel(const float* __restrict__ x, float* __restrict__ out) {
    // tid -> (b, ip, j4): ip = output row-pair index, j4 = group of 4 output cols
    const uint32_t tid = blockIdx.x * 256u + threadIdx.x;     // < 2^21
    const uint32_t j4 = tid & (QUADS_PER_ROW - 1);
    const uint32_t ip = (tid >> 8) & (ROWPAIRS - 1);          // output rows 2ip, 2ip+1
    const uint32_t b  = tid >> 17;

    // input rows 4ip .. 4ip+3, cols 8*j4 .. 8*j4+7
    const int64_t in_base = (int64_t)b * (H_ * W_) + (int64_t)(4 * ip) * W_ + 8 * j4;
    const float4* p = reinterpret_cast<const float4*>(x + in_base);
    const int rstep = W_ / 4;  // float4 stride per input row = 512

    // front-batch all 8 loads (MLP=8)
    float4 r0a = __ldcs(p);                 // row 4ip,   blocks 0,1
    float4 r0b = __ldcs(p + 1);             // row 4ip,   blocks 2,3
    float4 r1a = __ldcs(p + rstep);         // row 4ip+1
    float4 r1b = __ldcs(p + rstep + 1);
    float4 r2a = __ldcs(p + 2 * rstep);     // row 4ip+2
    float4 r2b = __ldcs(p + 2 * rstep + 1);
    float4 r3a = __ldcs(p + 3 * rstep);     // row 4ip+3
    float4 r3b = __ldcs(p + 3 * rstep + 1);

    const int64_t plane = (int64_t)B_ * HO * WO;   // 16M elems per subband
    const int64_t o0 = (int64_t)b * (HO * WO) + (int64_t)(2 * ip) * WO + 4 * j4;
    const int64_t o1 = o0 + WO;

    // output row 2ip (input rows 4ip, 4ip+1)
    #pragma unroll
    for (int s = 0; s < 4; s++) {
        float4 lo = haar_row(r0a, r1a, s);   // fills .x,.y = cols 0,1
        float4 hi = haar_row(r0b, r1b, s);   // fills .x,.y = cols 2,3
        float4 v; v.x = lo.x; v.y = lo.y; v.z = hi.x; v.w = hi.y;
        __stcs(reinterpret_cast<float4*>(out + s * plane + o0), v);
    }
    // output row 2ip+1 (input rows 4ip+2, 4ip+3)
    #pragma unroll
    for (int s = 0; s < 4; s++) {
        float4 lo = haar_row(r2a, r3a, s);
        float4 hi = haar_row(r2b, r3b, s);
        float4 v; v.x = lo.x; v.y = lo.y; v.z = hi.x; v.w = hi.y;
        __stcs(reinterpret_cast<float4*>(out + s * plane + o1), v);
    }
}

extern "C" void kernel_launch(void* const* d_in, const int* in_sizes, int n_in,
                              void* d_out, int out_size) {
    const float* x = (const float*)d_in[0];
    float* out = (float*)d_out;

    const int64_t total = (int64_t)B_ * ROWPAIRS * QUADS_PER_ROW;  // 2,097,152 threads
    const int threads = 256;
    const int blocks = (int)(total / threads);                     // 8192, exact
    dwt2d_haar_kernel<<<blocks, threads>>>(x, out);
}